// round 1
// baseline (speedup 1.0000x reference)
#include <cuda_runtime.h>
#include <cuda_bf16.h>

#define HH 512
#define WW 512
#define BATCH 32
#define TX 128
#define TY 32
#define TILE_W (TX + 6)   // 134
#define TILE_H (TY + 6)   // 38
#define SPITCH 136        // smem row pitch (floats)

__device__ double g_acc;

__global__ void ssim_zero_acc() { g_acc = 0.0; }

__global__ __launch_bounds__(TX) void ssim_main(const float* __restrict__ x,
                                                const float* __restrict__ y,
                                                const float* __restrict__ kern)
{
    __shared__ float sx[TILE_H][SPITCH];
    __shared__ float sy[TILE_H][SPITCH];
    __shared__ float wsum[4];

    const int tid  = threadIdx.x;
    const int col0 = blockIdx.x * TX;
    const int row0 = blockIdx.y * TY;
    const long base = (long)blockIdx.z * (HH * WW);

    // ---- stage x,y tile (with +/-3 halo, zero-padded) into smem ----
    for (int i = tid; i < TILE_H * TILE_W; i += TX) {
        int r = i / TILE_W;
        int c = i - r * TILE_W;
        int gr = row0 - 3 + r;
        int gc = col0 - 3 + c;
        float vx = 0.f, vy = 0.f;
        if (gr >= 0 && gr < HH && gc >= 0 && gc < WW) {
            long gi = base + (long)gr * WW + gc;
            vx = __ldg(x + gi);
            vy = __ldg(y + gi);
        }
        sx[r][c] = vx;
        sy[r][c] = vy;
    }

    // separable 1-D weights: k[i][j] = g_i g_j / S^2  =>  v_i = sqrt(k[i][i]) = g_i / S
    float w[7];
#pragma unroll
    for (int t = 0; t < 7; t++) w[t] = sqrtf(__ldg(kern + t * 7 + t));

    __syncthreads();

    // sliding 7-row window of horizontal conv results (5 maps)
    float hx[7], hy[7], hxx[7], hyy[7], hxy[7];
    float sum = 0.f;

    const float C1 = 1e-4f;   // 0.01^2
    const float C2 = 9e-4f;   // 0.03^2

    // horizontal 7-tap conv of (x, y, x^2, y^2, xy) at smem row r, column tid..tid+6
#define HCONV(r, A, B, CXX, CYY, CXY)                         \
    {                                                          \
        float a_ = 0.f, b_ = 0.f, cxx_ = 0.f, cyy_ = 0.f, cxy_ = 0.f; \
        _Pragma("unroll")                                      \
        for (int t = 0; t < 7; t++) {                          \
            float xv = sx[(r)][tid + t];                       \
            float yv = sy[(r)][tid + t];                       \
            float wt = w[t];                                   \
            float wx = wt * xv;                                \
            a_   = fmaf(wt, xv, a_);                           \
            b_   = fmaf(wt, yv, b_);                           \
            cxx_ = fmaf(wx, xv, cxx_);                         \
            cyy_ = fmaf(wt * yv, yv, cyy_);                    \
            cxy_ = fmaf(wx, yv, cxy_);                         \
        }                                                      \
        (A) = a_; (B) = b_; (CXX) = cxx_; (CYY) = cyy_; (CXY) = cxy_; \
    }

    // prologue: fill window slots 1..6 with halo rows 0..5 (slot 0 is shifted out
    // before first use)
#pragma unroll
    for (int r = 0; r < 6; r++) {
        HCONV(r, hx[r + 1], hy[r + 1], hxx[r + 1], hyy[r + 1], hxy[r + 1]);
    }
    hx[0] = hy[0] = hxx[0] = hyy[0] = hxy[0] = 0.f;

#pragma unroll 2
    for (int r = 6; r < TILE_H; r++) {
        // shift window
#pragma unroll
        for (int t = 0; t < 6; t++) {
            hx[t] = hx[t + 1];  hy[t] = hy[t + 1];
            hxx[t] = hxx[t + 1]; hyy[t] = hyy[t + 1]; hxy[t] = hxy[t + 1];
        }
        HCONV(r, hx[6], hy[6], hxx[6], hyy[6], hxy[6]);

        // vertical 7-tap conv
        float mx = 0.f, my = 0.f, exx = 0.f, eyy = 0.f, exy = 0.f;
#pragma unroll
        for (int t = 0; t < 7; t++) {
            float wt = w[t];
            mx  = fmaf(wt, hx[t],  mx);
            my  = fmaf(wt, hy[t],  my);
            exx = fmaf(wt, hxx[t], exx);
            eyy = fmaf(wt, hyy[t], eyy);
            exy = fmaf(wt, hxy[t], exy);
        }

        float sxx = exx - mx * mx;
        float syy = eyy - my * my;
        float sxy = exy - mx * my;
        float num = (2.f * mx * my + C1) * (2.f * sxy + C2);
        float den = (mx * mx + my * my + C1) * (sxx + syy + C2);
        sum += __fdividef(num, den);
    }
#undef HCONV

    // ---- block reduction ----
#pragma unroll
    for (int off = 16; off; off >>= 1)
        sum += __shfl_down_sync(0xffffffffu, sum, off);
    if ((tid & 31) == 0) wsum[tid >> 5] = sum;
    __syncthreads();
    if (tid == 0) {
        float s = wsum[0] + wsum[1] + wsum[2] + wsum[3];
        atomicAdd(&g_acc, (double)s);
    }
}

__global__ void ssim_finalize(float* __restrict__ out)
{
    out[0] = (float)(g_acc * (1.0 / ((double)BATCH * HH * WW)));
}

extern "C" void kernel_launch(void* const* d_in, const int* in_sizes, int n_in,
                              void* d_out, int out_size)
{
    const float* x = (const float*)d_in[0];
    const float* y = (const float*)d_in[1];
    const float* k = (const float*)d_in[2];
    float* out = (float*)d_out;

    ssim_zero_acc<<<1, 1>>>();
    dim3 grid(WW / TX, HH / TY, BATCH);
    ssim_main<<<grid, TX>>>(x, y, k);
    ssim_finalize<<<1, 1>>>(out);
}

// round 2
// speedup vs baseline: 1.1758x; 1.1758x over previous
#include <cuda_runtime.h>
#include <cuda_bf16.h>

#define HH 512
#define WW 512
#define BATCH 32
#define THREADS 128
#define OUTW 256          // output columns per tile (2 per thread)
#define OUTH 16           // output rows per tile
#define TILE_W (OUTW + 6) // 262
#define TILE_H (OUTH + 6) // 22
#define SPITCH 264        // smem row pitch in floats (8-aligned)

typedef unsigned long long u64;

__device__ double g_acc;

// ---- packed f32x2 helpers ----
static __device__ __forceinline__ u64 fma2_(u64 a, u64 b, u64 c) {
    u64 d; asm("fma.rn.f32x2 %0,%1,%2,%3;" : "=l"(d) : "l"(a), "l"(b), "l"(c)); return d;
}
static __device__ __forceinline__ u64 mul2_(u64 a, u64 b) {
    u64 d; asm("mul.rn.f32x2 %0,%1,%2;" : "=l"(d) : "l"(a), "l"(b)); return d;
}
static __device__ __forceinline__ u64 add2_(u64 a, u64 b) {
    u64 d; asm("add.rn.f32x2 %0,%1,%2;" : "=l"(d) : "l"(a), "l"(b)); return d;
}
static __device__ __forceinline__ u64 pk2(float lo, float hi) {
    u64 r; asm("mov.b64 %0,{%1,%2};" : "=l"(r) : "f"(lo), "f"(hi)); return r;
}
static __device__ __forceinline__ void upk2(u64 v, float& lo, float& hi) {
    asm("mov.b64 {%0,%1},%2;" : "=f"(lo), "=f"(hi) : "l"(v));
}
static __device__ __forceinline__ u64 neg2_(u64 a) { return a ^ 0x8000000080000000ULL; }
// pair {hi(a), lo(b)} — pure register re-pairing
static __device__ __forceinline__ u64 sh2_(u64 a, u64 b) { return (a >> 32) | (b << 32); }

__global__ void ssim_zero_acc() { g_acc = 0.0; }

__global__ __launch_bounds__(THREADS, 3) void ssim_main(const float* __restrict__ x,
                                                        const float* __restrict__ y,
                                                        const float* __restrict__ kern)
{
    __shared__ float sx[TILE_H][SPITCH];
    __shared__ float sy[TILE_H][SPITCH];
    __shared__ float wsum[4];

    const int tid  = threadIdx.x;
    const int col0 = blockIdx.x * OUTW;
    const int row0 = blockIdx.y * OUTH;
    const long base = (long)blockIdx.z * (HH * WW);

    // separable weights (k[i][j] = v_i v_j, v_i = sqrt(k[i][i]))
    u64 w2[7];
#pragma unroll
    for (int t = 0; t < 7; t++) {
        float wt = sqrtf(__ldg(kern + t * 7 + t));
        w2[t] = pk2(wt, wt);
    }

    // ---- stage x,y tile (with +/-3 halo, zero-padded) ----
    for (int i = tid; i < TILE_H * TILE_W; i += THREADS) {
        int r = i / TILE_W;
        int c = i - r * TILE_W;
        int gr = row0 - 3 + r;
        int gc = col0 - 3 + c;
        float vx = 0.f, vy = 0.f;
        if (gr >= 0 && gr < HH && gc >= 0 && gc < WW) {
            long gi = base + (long)gr * WW + gc;
            vx = __ldg(x + gi);
            vy = __ldg(y + gi);
        }
        sx[r][c] = vx;
        sy[r][c] = vy;
    }
    __syncthreads();

    const u64 two2 = pk2(2.f, 2.f);
    const u64 c1_2 = pk2(1e-4f, 1e-4f);
    const u64 c2_2 = pk2(9e-4f, 9e-4f);

    // rotating 7-row window of packed horizontal-conv results, slot = row % 7
    u64 Wx[7], Wy[7], Wxx[7], Wyy[7], Wxy[7];
    float sum = 0.f;

    // horizontal 7-tap conv of (x,y,xx,yy,xy) at row r -> packed pair for cols (2tid, 2tid+1)
#define HCONV(r, s)                                                          \
    {                                                                        \
        const float* rx_ = &sx[(r)][2 * tid];                                \
        const float* ry_ = &sy[(r)][2 * tid];                                \
        u64 ex0 = *(const u64*)(rx_ + 0), ex1 = *(const u64*)(rx_ + 2);      \
        u64 ex2 = *(const u64*)(rx_ + 4), ex3 = *(const u64*)(rx_ + 6);     \
        u64 ey0 = *(const u64*)(ry_ + 0), ey1 = *(const u64*)(ry_ + 2);      \
        u64 ey2 = *(const u64*)(ry_ + 4), ey3 = *(const u64*)(ry_ + 6);     \
        u64 xp[7] = {ex0, sh2_(ex0, ex1), ex1, sh2_(ex1, ex2),               \
                     ex2, sh2_(ex2, ex3), ex3};                              \
        u64 yp[7] = {ey0, sh2_(ey0, ey1), ey1, sh2_(ey1, ey2),               \
                     ey2, sh2_(ey2, ey3), ey3};                              \
        u64 wx0 = mul2_(w2[0], xp[0]);                                       \
        u64 wy0 = mul2_(w2[0], yp[0]);                                       \
        u64 a_  = wx0, b_ = wy0;                                             \
        u64 cxx_ = mul2_(wx0, xp[0]);                                        \
        u64 cyy_ = mul2_(wy0, yp[0]);                                        \
        u64 cxy_ = mul2_(wx0, yp[0]);                                        \
        _Pragma("unroll")                                                    \
        for (int t = 1; t < 7; t++) {                                        \
            u64 wx = mul2_(w2[t], xp[t]);                                    \
            u64 wy = mul2_(w2[t], yp[t]);                                    \
            a_   = add2_(a_, wx);                                            \
            b_   = add2_(b_, wy);                                            \
            cxx_ = fma2_(wx, xp[t], cxx_);                                   \
            cyy_ = fma2_(wy, yp[t], cyy_);                                   \
            cxy_ = fma2_(wx, yp[t], cxy_);                                   \
        }                                                                    \
        Wx[(s)] = a_; Wy[(s)] = b_;                                          \
        Wxx[(s)] = cxx_; Wyy[(s)] = cyy_; Wxy[(s)] = cxy_;                   \
    }

    // prologue: halo rows 0..5 fill slots 0..5
#pragma unroll
    for (int r = 0; r < 6; r++) {
        HCONV(r, r);
    }

#pragma unroll
    for (int r = 6; r < TILE_H; r++) {
        HCONV(r, r % 7);

        // vertical 7-tap conv over window rows (r-6 .. r), slot = row % 7
        u64 mx  = mul2_(w2[0], Wx[(r - 6) % 7]);
        u64 my  = mul2_(w2[0], Wy[(r - 6) % 7]);
        u64 exx = mul2_(w2[0], Wxx[(r - 6) % 7]);
        u64 eyy = mul2_(w2[0], Wyy[(r - 6) % 7]);
        u64 exy = mul2_(w2[0], Wxy[(r - 6) % 7]);
#pragma unroll
        for (int t = 1; t < 7; t++) {
            int s = (r - 6 + t) % 7;
            mx  = fma2_(w2[t], Wx[s],  mx);
            my  = fma2_(w2[t], Wy[s],  my);
            exx = fma2_(w2[t], Wxx[s], exx);
            eyy = fma2_(w2[t], Wyy[s], eyy);
            exy = fma2_(w2[t], Wxy[s], exy);
        }

        // SSIM pointwise (packed)
        u64 nmx = neg2_(mx);
        u64 sxx = fma2_(nmx, mx, exx);
        u64 syy = fma2_(neg2_(my), my, eyy);
        u64 sxy = fma2_(nmx, my, exy);

        u64 mxmy = mul2_(mx, my);
        u64 n1 = fma2_(two2, mxmy, c1_2);      // 2 mx my + C1
        u64 n2 = fma2_(two2, sxy, c2_2);       // 2 sxy + C2
        u64 num = mul2_(n1, n2);

        u64 myy = mul2_(my, my);
        u64 d1 = fma2_(mx, mx, myy);           // mx^2 + my^2
        d1 = add2_(d1, c1_2);
        u64 d2 = add2_(add2_(sxx, syy), c2_2);
        u64 den = mul2_(d1, d2);

        float nlo, nhi, dlo, dhi;
        upk2(num, nlo, nhi);
        upk2(den, dlo, dhi);
        sum += __fdividef(nlo, dlo) + __fdividef(nhi, dhi);
    }
#undef HCONV

    // ---- block reduction ----
#pragma unroll
    for (int off = 16; off; off >>= 1)
        sum += __shfl_down_sync(0xffffffffu, sum, off);
    if ((tid & 31) == 0) wsum[tid >> 5] = sum;
    __syncthreads();
    if (tid == 0) {
        float s = wsum[0] + wsum[1] + wsum[2] + wsum[3];
        atomicAdd(&g_acc, (double)s);
    }
}

__global__ void ssim_finalize(float* __restrict__ out)
{
    out[0] = (float)(g_acc * (1.0 / ((double)BATCH * HH * WW)));
}

extern "C" void kernel_launch(void* const* d_in, const int* in_sizes, int n_in,
                              void* d_out, int out_size)
{
    const float* x = (const float*)d_in[0];
    const float* y = (const float*)d_in[1];
    const float* k = (const float*)d_in[2];
    float* out = (float*)d_out;

    ssim_zero_acc<<<1, 1>>>();
    dim3 grid(WW / OUTW, HH / OUTH, BATCH);
    ssim_main<<<grid, THREADS>>>(x, y, k);
    ssim_finalize<<<1, 1>>>(out);
}